// round 9
// baseline (speedup 1.0000x reference)
#include <cuda_runtime.h>
#include <cuda_fp16.h>

#define NN 100000
#define EE 1600000
#define MAXDEG 128
#define NEG_SLOPE 0.2f

// ---------------- scratch (static device globals; no allocation) ----------------
__device__ int    g_deg[NN];
__device__ int    g_csr[(size_t)NN * MAXDEG];   // padded CSR: src list per dst
__device__ float  g_w[(size_t)NN * MAXDEG];     // per-slot edge weights (0 in pad)
__device__ __half g_featH[(size_t)NN * 32];     // layer-1 features (fp16, 64B rows)
__device__ float  g_el[NN], g_er[NN];
__device__ __half g_feat2H[(size_t)NN * 32];    // layer-2 features (fp16)
__device__ float  g_el2[NN], g_er2[NN];

// ---------------- build: zero degrees, then direct scatter ----------------
__global__ void k_zero(int N) {
    int i = blockIdx.x * blockDim.x + threadIdx.x;
    if (i < N) g_deg[i] = 0;
}

__global__ void k_scatter(const int* __restrict__ src, const int* __restrict__ dst, int E) {
    int i = (blockIdx.x * blockDim.x + threadIdx.x) * 4;
    if (i + 3 < E) {
        int4 s = *(const int4*)(src + i);
        int4 d = *(const int4*)(dst + i);
        int p0 = atomicAdd(&g_deg[d.x], 1);
        int p1 = atomicAdd(&g_deg[d.y], 1);
        int p2 = atomicAdd(&g_deg[d.z], 1);
        int p3 = atomicAdd(&g_deg[d.w], 1);
        if (p0 < MAXDEG) g_csr[(size_t)d.x * MAXDEG + p0] = s.x;
        if (p1 < MAXDEG) g_csr[(size_t)d.y * MAXDEG + p1] = s.y;
        if (p2 < MAXDEG) g_csr[(size_t)d.z * MAXDEG + p2] = s.z;
        if (p3 < MAXDEG) g_csr[(size_t)d.w * MAXDEG + p3] = s.w;
    } else {
        for (; i < E; i++) {
            int d = dst[i];
            int p = atomicAdd(&g_deg[d], 1);
            if (p < MAXDEG) g_csr[(size_t)d * MAXDEG + p] = src[i];
        }
    }
}

// ---------------- GEMM1 + attention projections (DIN=128) ----------------
__global__ void __launch_bounds__(256) k_gemm_attn(
        const float* __restrict__ h,
        const float* __restrict__ W,
        const float* __restrict__ al,
        const float* __restrict__ ar,
        int N) {
    constexpr int Q = 32;
    __shared__ float4 Wt4[Q * 32];
    __shared__ float4 hs4[8][4 * Q];
    __shared__ float sal[32], sar[32];

    int tid = threadIdx.x;
    for (int i = tid; i < Q * 32; i += 256) {
        int f = i / Q, q = i - f * Q;
        Wt4[q * 32 + f] = ((const float4*)W)[i];
    }
    if (tid < 32) { sal[tid] = al[tid]; sar[tid] = ar[tid]; }
    __syncthreads();

    int warp = tid >> 5, lane = tid & 31;
    int nbase = blockIdx.x * 32 + warp * 4;
    float4* hw = hs4[warp];

#pragma unroll
    for (int j = 0; j < 4; j++) {
        int n = nbase + j;
        if (n < N) hw[j * Q + lane] = ((const float4*)(h + (size_t)n * 128))[lane];
    }
    __syncwarp();

    float acc[4] = {0.f, 0.f, 0.f, 0.f};
#pragma unroll 4
    for (int q = 0; q < Q; q++) {
        float4 w4 = Wt4[q * 32 + lane];
#pragma unroll
        for (int j = 0; j < 4; j++) {
            float4 h4 = hw[j * Q + q];
            acc[j] = fmaf(w4.x, h4.x, acc[j]);
            acc[j] = fmaf(w4.y, h4.y, acc[j]);
            acc[j] = fmaf(w4.z, h4.z, acc[j]);
            acc[j] = fmaf(w4.w, h4.w, acc[j]);
        }
    }

#pragma unroll
    for (int j = 0; j < 4; j++) {
        int n = nbase + j;
        if (n >= N) break;
        g_featH[(size_t)n * 32 + lane] = __float2half_rn(acc[j]);
        float vl = acc[j] * sal[lane];
        float vr = acc[j] * sar[lane];
#pragma unroll
        for (int o = 16; o; o >>= 1) {
            vl += __shfl_xor_sync(0xffffffffu, vl, o);
            vr += __shfl_xor_sync(0xffffffffu, vr, o);
        }
        if (lane == 0) { g_el[n] = vl; g_er[n] = vr; }
    }
}

// ---------------- per-slot edge weights (layer selected by flag) ------------
// warp per node; computes w = exp(lrelu(el[s]+er[n])) for valid slots,
// zero-pads w and csr up to the next multiple of 16 (aggregate reads pad-free).
__global__ void __launch_bounds__(256) k_weights(int layer2, int N) {
    int n = (blockIdx.x * blockDim.x + threadIdx.x) >> 5;
    if (n >= N) return;
    int lane = threadIdx.x & 31;

    const float* el = layer2 ? g_el2 : g_el;
    float ern = (layer2 ? g_er2 : g_er)[n];

    int cnt = g_deg[n];
    if (cnt > MAXDEG) cnt = MAXDEG;
    int pad = (cnt + 15) & ~15;
    if (pad > MAXDEG) pad = MAXDEG;

    int* csr = g_csr + (size_t)n * MAXDEG;
    float* wv = g_w + (size_t)n * MAXDEG;

    for (int j = lane; j < pad; j += 32) {
        float w = 0.f;
        if (j < cnt) {
            int s = csr[j];
            float e = el[s] + ern;
            e = (e >= 0.f) ? e : NEG_SLOPE * e;
            w = __expf(fminf(e, 80.f));
        } else {
            csr[j] = 0;                // safe gather address for pad slots
        }
        wv[j] = w;
    }
}

// ---- shared edge-loop: no shfl, no mufu; 16-edge blocks, batched loads -----
// 4 edge-groups (g) x 8 feature-lanes (r). Broadcast loads of w and s
// (4 consecutive words -> 1 sector each), 4 independent 64B feature gathers.
// ssum is accumulated by all 8 lanes of each group (x8 overcount, fixed by 8/ssum).
__device__ __forceinline__ void edge_loop(
        const int* __restrict__ csr, const float* __restrict__ wv,
        const uint2* __restrict__ featH, int cnt, int g, int r,
        float& ssum, float4& acc) {
    for (int jb = 0; jb < cnt; jb += 16) {
        int b = jb + g;
        float w0 = wv[b];
        float w1 = wv[b + 4];
        float w2 = wv[b + 8];
        float w3 = wv[b + 12];
        int s0 = csr[b];
        int s1 = csr[b + 4];
        int s2 = csr[b + 8];
        int s3 = csr[b + 12];
        uint2 p0 = featH[(size_t)s0 * 8 + r];
        uint2 p1 = featH[(size_t)s1 * 8 + r];
        uint2 p2 = featH[(size_t)s2 * 8 + r];
        uint2 p3 = featH[(size_t)s3 * 8 + r];
        ssum += (w0 + w1) + (w2 + w3);
        float2 a, bb;
        a = __half22float2(*(__half2*)&p0.x); bb = __half22float2(*(__half2*)&p0.y);
        acc.x = fmaf(w0, a.x, acc.x); acc.y = fmaf(w0, a.y, acc.y);
        acc.z = fmaf(w0, bb.x, acc.z); acc.w = fmaf(w0, bb.y, acc.w);
        a = __half22float2(*(__half2*)&p1.x); bb = __half22float2(*(__half2*)&p1.y);
        acc.x = fmaf(w1, a.x, acc.x); acc.y = fmaf(w1, a.y, acc.y);
        acc.z = fmaf(w1, bb.x, acc.z); acc.w = fmaf(w1, bb.y, acc.w);
        a = __half22float2(*(__half2*)&p2.x); bb = __half22float2(*(__half2*)&p2.y);
        acc.x = fmaf(w2, a.x, acc.x); acc.y = fmaf(w2, a.y, acc.y);
        acc.z = fmaf(w2, bb.x, acc.z); acc.w = fmaf(w2, bb.y, acc.w);
        a = __half22float2(*(__half2*)&p3.x); bb = __half22float2(*(__half2*)&p3.y);
        acc.x = fmaf(w3, a.x, acc.x); acc.y = fmaf(w3, a.y, acc.y);
        acc.z = fmaf(w3, bb.x, acc.z); acc.w = fmaf(w3, bb.y, acc.w);
    }
    // reduce: ssum over all 32 lanes (x8 overcount), acc over 4 groups
#pragma unroll
    for (int o = 16; o; o >>= 1) ssum += __shfl_xor_sync(0xffffffffu, ssum, o);
#pragma unroll
    for (int o = 8; o <= 16; o <<= 1) {
        acc.x += __shfl_xor_sync(0xffffffffu, acc.x, o);
        acc.y += __shfl_xor_sync(0xffffffffu, acc.y, o);
        acc.z += __shfl_xor_sync(0xffffffffu, acc.z, o);
        acc.w += __shfl_xor_sync(0xffffffffu, acc.w, o);
    }
}

// ---------------- fused: aggregate layer1 + GEMM2 + attn proj layer2 ----------
__global__ void __launch_bounds__(256) k_agg1_gemm2(
        const float* __restrict__ b1,
        const float* __restrict__ W2,
        const float* __restrict__ al2,
        const float* __restrict__ ar2,
        int N) {
    __shared__ float4 W2t4[8 * 32];
    __shared__ float sal[32], sar[32];
    __shared__ float rowbuf[8][32];

    int tid = threadIdx.x;
    for (int i = tid; i < 8 * 32; i += 256) {
        int f = i / 8, q = i - f * 8;
        W2t4[q * 32 + f] = ((const float4*)W2)[i];
    }
    if (tid < 32) { sal[tid] = al2[tid]; sar[tid] = ar2[tid]; }
    __syncthreads();

    int n = (blockIdx.x * blockDim.x + tid) >> 5;
    if (n >= N) return;
    int lane = tid & 31;
    int g = lane >> 3, r = lane & 7;
    int warp = tid >> 5;

    int cnt = g_deg[n];
    if (cnt > MAXDEG) cnt = MAXDEG;

    float ssum = 0.f;
    float4 acc = {0.f, 0.f, 0.f, 0.f};
    edge_loop(g_csr + (size_t)n * MAXDEG, g_w + (size_t)n * MAXDEG,
              (const uint2*)g_featH, cnt, g, r, ssum, acc);

    if (g == 0) {
        float4 bias4 = ((const float4*)b1)[r];
        float inv = (cnt > 0) ? (8.f / ssum) : 0.f;
        float4 o4;
        o4.x = fmaf(acc.x, inv, bias4.x);
        o4.y = fmaf(acc.y, inv, bias4.y);
        o4.z = fmaf(acc.z, inv, bias4.z);
        o4.w = fmaf(acc.w, inv, bias4.w);
        ((float4*)rowbuf[warp])[r] = o4;
    }
    __syncwarp();

    // GEMM2 for this node (fp32): feat2[lane] = dot(row, W2[lane][:])
    float a2 = 0.f;
#pragma unroll
    for (int q = 0; q < 8; q++) {
        float4 w4 = W2t4[q * 32 + lane];
        float4 h4 = ((const float4*)rowbuf[warp])[q];
        a2 = fmaf(w4.x, h4.x, a2);
        a2 = fmaf(w4.y, h4.y, a2);
        a2 = fmaf(w4.z, h4.z, a2);
        a2 = fmaf(w4.w, h4.w, a2);
    }
    g_feat2H[(size_t)n * 32 + lane] = __float2half_rn(a2);

    float vl = a2 * sal[lane];
    float vr = a2 * sar[lane];
#pragma unroll
    for (int o = 16; o; o >>= 1) {
        vl += __shfl_xor_sync(0xffffffffu, vl, o);
        vr += __shfl_xor_sync(0xffffffffu, vr, o);
    }
    if (lane == 0) { g_el2[n] = vl; g_er2[n] = vr; }
}

// ---------------- final aggregate (layer 2) ----------------
__global__ void __launch_bounds__(256) k_agg2(
        const float* __restrict__ b2,
        float* __restrict__ out,
        int N) {
    int n = (blockIdx.x * blockDim.x + threadIdx.x) >> 5;
    if (n >= N) return;
    int lane = threadIdx.x & 31;
    int g = lane >> 3, r = lane & 7;

    int cnt = g_deg[n];
    if (cnt > MAXDEG) cnt = MAXDEG;
    float4 bias4 = ((const float4*)b2)[r];
    float4* out4 = (float4*)out;

    if (cnt == 0) {
        if (g == 0) out4[(size_t)n * 8 + r] = bias4;
        return;
    }

    float ssum = 0.f;
    float4 acc = {0.f, 0.f, 0.f, 0.f};
    edge_loop(g_csr + (size_t)n * MAXDEG, g_w + (size_t)n * MAXDEG,
              (const uint2*)g_feat2H, cnt, g, r, ssum, acc);

    if (g == 0) {
        float inv = 8.f / ssum;
        float4 o4;
        o4.x = fmaf(acc.x, inv, bias4.x);
        o4.y = fmaf(acc.y, inv, bias4.y);
        o4.z = fmaf(acc.z, inv, bias4.z);
        o4.w = fmaf(acc.w, inv, bias4.w);
        out4[(size_t)n * 8 + r] = o4;
    }
}

// ---------------- driver ----------------
extern "C" void kernel_launch(void* const* d_in, const int* in_sizes, int n_in,
                              void* d_out, int out_size) {
    const float* features = (const float*)d_in[0];
    const int*   src      = (const int*)d_in[1];
    const int*   dst      = (const int*)d_in[2];
    const float* W1  = (const float*)d_in[3];
    const float* al1 = (const float*)d_in[4];
    const float* ar1 = (const float*)d_in[5];
    const float* b1  = (const float*)d_in[6];
    const float* W2  = (const float*)d_in[7];
    const float* al2 = (const float*)d_in[8];
    const float* ar2 = (const float*)d_in[9];
    const float* b2  = (const float*)d_in[10];

    int E = in_sizes[1];
    int N = in_sizes[0] / 128;
    if (N > NN) N = NN;
    if (E > EE) E = EE;

    float* out = (float*)d_out;

    static cudaStream_t s_side = nullptr;
    static cudaEvent_t ev_fork = nullptr, ev_join = nullptr;
    if (!s_side) {
        cudaStreamCreateWithFlags(&s_side, cudaStreamNonBlocking);
        cudaEventCreateWithFlags(&ev_fork, cudaEventDisableTiming);
        cudaEventCreateWithFlags(&ev_join, cudaEventDisableTiming);
    }

    const int T = 256;
    int gN = (N + T - 1) / T;
    int gE4 = (E / 4 + T) / T + 1;
    int gGemm = (N + 31) / 32;
    int gWarp = (N + 7) / 8;

    // fork: GEMM1 runs concurrently with CSR build
    cudaEventRecord(ev_fork, 0);
    cudaStreamWaitEvent(s_side, ev_fork, 0);
    k_gemm_attn<<<gGemm, T, 0, s_side>>>(features, W1, al1, ar1, N);
    cudaEventRecord(ev_join, s_side);

    k_zero<<<gN, T>>>(N);
    k_scatter<<<gE4, T>>>(src, dst, E);

    cudaStreamWaitEvent(0, ev_join, 0);

    // layer 1: weights, then aggregate fused with GEMM2 + projections
    k_weights<<<gWarp, T>>>(0, N);
    k_agg1_gemm2<<<gWarp, T>>>(b1, W2, al2, ar2, N);
    // layer 2: weights, then final aggregate
    k_weights<<<gWarp, T>>>(1, N);
    k_agg2<<<gWarp, T>>>(b2, out, N);
}

// round 10
// speedup vs baseline: 1.1690x; 1.1690x over previous
#include <cuda_runtime.h>
#include <cuda_fp16.h>

#define NN 100000
#define EE 1600000
#define MAXDEG 128
#define NEG_SLOPE 0.2f

// ---------------- scratch (static device globals; no allocation) ----------------
__device__ int    g_deg[NN];
__device__ int    g_csr[(size_t)NN * MAXDEG];   // padded CSR: src list per dst
__device__ __half g_featH[(size_t)NN * 32];     // layer-1 features (fp16, 64B rows)
__device__ float  g_el[NN], g_er[NN];
__device__ float  g_out1[(size_t)NN * 32];      // layer-1 output (fp32)
__device__ __half g_feat2H[(size_t)NN * 32];    // layer-2 features (fp16)
__device__ float  g_el2[NN], g_er2[NN];

// ---------------- build: zero degrees, then direct scatter ----------------
__global__ void k_zero(int N) {
    int i = blockIdx.x * blockDim.x + threadIdx.x;
    if (i < N) g_deg[i] = 0;
}

__global__ void k_scatter(const int* __restrict__ src, const int* __restrict__ dst, int E) {
    int i = (blockIdx.x * blockDim.x + threadIdx.x) * 4;
    if (i + 3 < E) {
        int4 s = *(const int4*)(src + i);
        int4 d = *(const int4*)(dst + i);
        int p0 = atomicAdd(&g_deg[d.x], 1);
        int p1 = atomicAdd(&g_deg[d.y], 1);
        int p2 = atomicAdd(&g_deg[d.z], 1);
        int p3 = atomicAdd(&g_deg[d.w], 1);
        if (p0 < MAXDEG) g_csr[(size_t)d.x * MAXDEG + p0] = s.x;
        if (p1 < MAXDEG) g_csr[(size_t)d.y * MAXDEG + p1] = s.y;
        if (p2 < MAXDEG) g_csr[(size_t)d.z * MAXDEG + p2] = s.z;
        if (p3 < MAXDEG) g_csr[(size_t)d.w * MAXDEG + p3] = s.w;
    } else {
        for (; i < E; i++) {
            int d = dst[i];
            int p = atomicAdd(&g_deg[d], 1);
            if (p < MAXDEG) g_csr[(size_t)d * MAXDEG + p] = src[i];
        }
    }
}

// ---------------- GEMM + attention projections (templated) ----------------
// DIN=128: reads external features, writes g_featH/g_el/g_er (layer 1).
// DIN=32, L2OUT=1: reads g_out1, writes g_feat2H/g_el2/g_er2 (layer 2).
// Warp computes 4 nodes (register-blocked), lane = output feature.
template <int DIN, int L2OUT>
__global__ void __launch_bounds__(256) k_gemm_attn(
        const float* __restrict__ h_ext,
        const float* __restrict__ W,
        const float* __restrict__ al,
        const float* __restrict__ ar,
        int N) {
    constexpr int Q = DIN / 4;
    __shared__ float4 Wt4[Q * 32];
    __shared__ float4 hs4[8][4 * Q];
    __shared__ float sal[32], sar[32];

    const float* h = L2OUT ? g_out1 : h_ext;
    __half* featH = L2OUT ? g_feat2H : g_featH;
    float* elp = L2OUT ? g_el2 : g_el;
    float* erp = L2OUT ? g_er2 : g_er;

    int tid = threadIdx.x;
    for (int i = tid; i < Q * 32; i += 256) {
        int f = i / Q, q = i - f * Q;
        Wt4[q * 32 + f] = ((const float4*)W)[i];
    }
    if (tid < 32) { sal[tid] = al[tid]; sar[tid] = ar[tid]; }
    __syncthreads();

    int warp = tid >> 5, lane = tid & 31;
    int nbase = blockIdx.x * 32 + warp * 4;
    float4* hw = hs4[warp];

#pragma unroll
    for (int j = 0; j < 4; j++) {
        int n = nbase + j;
        if (n < N) {
            if (DIN == 128) {
                hw[j * Q + lane] = ((const float4*)(h + (size_t)n * DIN))[lane];
            } else {
                if (lane < Q)
                    hw[j * Q + lane] = ((const float4*)(h + (size_t)n * DIN))[lane];
            }
        }
    }
    __syncwarp();

    float acc[4] = {0.f, 0.f, 0.f, 0.f};
#pragma unroll 4
    for (int q = 0; q < Q; q++) {
        float4 w4 = Wt4[q * 32 + lane];
#pragma unroll
        for (int j = 0; j < 4; j++) {
            float4 h4 = hw[j * Q + q];
            acc[j] = fmaf(w4.x, h4.x, acc[j]);
            acc[j] = fmaf(w4.y, h4.y, acc[j]);
            acc[j] = fmaf(w4.z, h4.z, acc[j]);
            acc[j] = fmaf(w4.w, h4.w, acc[j]);
        }
    }

#pragma unroll
    for (int j = 0; j < 4; j++) {
        int n = nbase + j;
        if (n >= N) break;
        featH[(size_t)n * 32 + lane] = __float2half_rn(acc[j]);
        float vl = acc[j] * sal[lane];
        float vr = acc[j] * sar[lane];
#pragma unroll
        for (int o = 16; o; o >>= 1) {
            vl += __shfl_xor_sync(0xffffffffu, vl, o);
            vr += __shfl_xor_sync(0xffffffffu, vr, o);
        }
        if (lane == 0) { elp[n] = vl; erp[n] = vr; }
    }
}

// ---- shared edge-loop (two-phase, warp per node, fp16 feature gathers) -----
// Phase 1: lane=edge (1 csr load, 1 el gather, 1 exp).
// Phase 2: 4 edge-groups x 8 feature-lanes; lane r loads uint2 = 4 halfs.
__device__ __forceinline__ void edge_loop(
        const int* __restrict__ csr, int cnt,
        const float* __restrict__ el, const uint2* __restrict__ featH,
        float ern, int lane, int g, int r,
        float& ssum, float4& acc) {
    for (int j0 = 0; j0 < cnt; j0 += 32) {
        int j = j0 + lane;
        bool v = j < cnt;
        int s = csr[v ? j : 0];
        float e = el[s] + ern;
        e = (e >= 0.f) ? e : NEG_SLOPE * e;
        float w = v ? __expf(e) : 0.f;
        ssum += w;
        int kmax = cnt - j0; if (kmax > 32) kmax = 32;
        for (int k = 0; k < kmax; k += 4) {
            int srcl = k + g;
            int   sk = __shfl_sync(0xffffffffu, s, srcl);
            float wk = __shfl_sync(0xffffffffu, w, srcl);
            uint2 p = featH[(size_t)sk * 8 + r];     // 4 halfs, 64B row
            float2 f01 = __half22float2(*(__half2*)&p.x);
            float2 f23 = __half22float2(*(__half2*)&p.y);
            acc.x = fmaf(wk, f01.x, acc.x);
            acc.y = fmaf(wk, f01.y, acc.y);
            acc.z = fmaf(wk, f23.x, acc.z);
            acc.w = fmaf(wk, f23.y, acc.w);
        }
    }
#pragma unroll
    for (int o = 16; o; o >>= 1) ssum += __shfl_xor_sync(0xffffffffu, ssum, o);
#pragma unroll
    for (int o = 8; o <= 16; o <<= 1) {
        acc.x += __shfl_xor_sync(0xffffffffu, acc.x, o);
        acc.y += __shfl_xor_sync(0xffffffffu, acc.y, o);
        acc.z += __shfl_xor_sync(0xffffffffu, acc.z, o);
        acc.w += __shfl_xor_sync(0xffffffffu, acc.w, o);
    }
}

// ---------------- layer-1 aggregate (minimal: loop + reduce + fp32 out) -----
__global__ void __launch_bounds__(256) k_agg1(
        const float* __restrict__ b1, int N) {
    int n = (blockIdx.x * blockDim.x + threadIdx.x) >> 5;
    if (n >= N) return;
    int lane = threadIdx.x & 31;
    int g = lane >> 3, r = lane & 7;

    int cnt = g_deg[n];
    if (cnt > MAXDEG) cnt = MAXDEG;
    float4* out4 = (float4*)g_out1;

    if (cnt == 0) {
        if (g == 0) out4[(size_t)n * 8 + r] = ((const float4*)b1)[r];
        return;
    }

    float ssum = 0.f;
    float4 acc = {0.f, 0.f, 0.f, 0.f};
    edge_loop(g_csr + (size_t)n * MAXDEG, cnt, g_el,
              (const uint2*)g_featH, g_er[n], lane, g, r, ssum, acc);

    if (g == 0) {
        float4 bias4 = ((const float4*)b1)[r];
        float inv = 1.f / ssum;
        float4 o4;
        o4.x = fmaf(acc.x, inv, bias4.x);
        o4.y = fmaf(acc.y, inv, bias4.y);
        o4.z = fmaf(acc.z, inv, bias4.z);
        o4.w = fmaf(acc.w, inv, bias4.w);
        out4[(size_t)n * 8 + r] = o4;
    }
}

// ---------------- layer-2 aggregate (final output) ----------------
__global__ void __launch_bounds__(256) k_agg2(
        const float* __restrict__ b2,
        float* __restrict__ out,
        int N) {
    int n = (blockIdx.x * blockDim.x + threadIdx.x) >> 5;
    if (n >= N) return;
    int lane = threadIdx.x & 31;
    int g = lane >> 3, r = lane & 7;

    int cnt = g_deg[n];
    if (cnt > MAXDEG) cnt = MAXDEG;
    float4* out4 = (float4*)out;

    if (cnt == 0) {
        if (g == 0) out4[(size_t)n * 8 + r] = ((const float4*)b2)[r];
        return;
    }

    float ssum = 0.f;
    float4 acc = {0.f, 0.f, 0.f, 0.f};
    edge_loop(g_csr + (size_t)n * MAXDEG, cnt, g_el2,
              (const uint2*)g_feat2H, g_er2[n], lane, g, r, ssum, acc);

    if (g == 0) {
        float4 bias4 = ((const float4*)b2)[r];
        float inv = 1.f / ssum;
        float4 o4;
        o4.x = fmaf(acc.x, inv, bias4.x);
        o4.y = fmaf(acc.y, inv, bias4.y);
        o4.z = fmaf(acc.z, inv, bias4.z);
        o4.w = fmaf(acc.w, inv, bias4.w);
        out4[(size_t)n * 8 + r] = o4;
    }
}

// ---------------- driver ----------------
extern "C" void kernel_launch(void* const* d_in, const int* in_sizes, int n_in,
                              void* d_out, int out_size) {
    const float* features = (const float*)d_in[0];
    const int*   src      = (const int*)d_in[1];
    const int*   dst      = (const int*)d_in[2];
    const float* W1  = (const float*)d_in[3];
    const float* al1 = (const float*)d_in[4];
    const float* ar1 = (const float*)d_in[5];
    const float* b1  = (const float*)d_in[6];
    const float* W2  = (const float*)d_in[7];
    const float* al2 = (const float*)d_in[8];
    const float* ar2 = (const float*)d_in[9];
    const float* b2  = (const float*)d_in[10];

    int E = in_sizes[1];
    int N = in_sizes[0] / 128;
    if (N > NN) N = NN;
    if (E > EE) E = EE;

    float* out = (float*)d_out;

    static cudaStream_t s_side = nullptr;
    static cudaEvent_t ev_fork = nullptr, ev_join = nullptr;
    if (!s_side) {
        cudaStreamCreateWithFlags(&s_side, cudaStreamNonBlocking);
        cudaEventCreateWithFlags(&ev_fork, cudaEventDisableTiming);
        cudaEventCreateWithFlags(&ev_join, cudaEventDisableTiming);
    }

    const int T = 256;
    int gN = (N + T - 1) / T;
    int gE4 = (E / 4 + T) / T + 1;
    int gGemm = (N + 31) / 32;
    int gWarp = (N + 7) / 8;

    // fork: GEMM1 runs concurrently with CSR build
    cudaEventRecord(ev_fork, 0);
    cudaStreamWaitEvent(s_side, ev_fork, 0);
    k_gemm_attn<128, 0><<<gGemm, T, 0, s_side>>>(features, W1, al1, ar1, N);
    cudaEventRecord(ev_join, s_side);

    k_zero<<<gN, T>>>(N);
    k_scatter<<<gE4, T>>>(src, dst, E);

    cudaStreamWaitEvent(0, ev_join, 0);

    // layer 1 aggregate -> fp32 out1
    k_agg1<<<gWarp, T>>>(b1, N);
    // GEMM2 + layer-2 projections (register-blocked, 4 nodes/warp)
    k_gemm_attn<32, 1><<<gGemm, T>>>(nullptr, W2, al2, ar2, N);
    // layer 2 aggregate -> final output
    k_agg2<<<gWarp, T>>>(b2, out, N);
}

// round 12
// speedup vs baseline: 1.2447x; 1.0647x over previous
#include <cuda_runtime.h>
#include <cuda_fp16.h>

#define NN 100000
#define EE 1600000
#define MAXDEG 128
#define NEG_SLOPE 0.2f

// ---------------- scratch (static device globals; no allocation) ----------------
__device__ int    g_deg[NN];
__device__ int    g_csr[(size_t)NN * MAXDEG];   // padded CSR: src list per dst
__device__ __half g_featH[(size_t)NN * 32];     // layer-1 features (fp16, 64B rows)
__device__ float  g_el[NN], g_er[NN];
__device__ float  g_out1[(size_t)NN * 32];      // layer-1 output (fp32)
__device__ __half g_feat2H[(size_t)NN * 32];    // layer-2 features (fp16)
__device__ float  g_el2[NN], g_er2[NN];

// ---------------- build: zero degrees, then direct scatter ----------------
__global__ void k_zero(int N) {
    int i = blockIdx.x * blockDim.x + threadIdx.x;
    if (i < N) g_deg[i] = 0;
}

__global__ void k_scatter(const int* __restrict__ src, const int* __restrict__ dst, int E) {
    int i = (blockIdx.x * blockDim.x + threadIdx.x) * 4;
    if (i + 3 < E) {
        int4 s = *(const int4*)(src + i);
        int4 d = *(const int4*)(dst + i);
        int p0 = atomicAdd(&g_deg[d.x], 1);
        int p1 = atomicAdd(&g_deg[d.y], 1);
        int p2 = atomicAdd(&g_deg[d.z], 1);
        int p3 = atomicAdd(&g_deg[d.w], 1);
        if (p0 < MAXDEG) g_csr[(size_t)d.x * MAXDEG + p0] = s.x;
        if (p1 < MAXDEG) g_csr[(size_t)d.y * MAXDEG + p1] = s.y;
        if (p2 < MAXDEG) g_csr[(size_t)d.z * MAXDEG + p2] = s.z;
        if (p3 < MAXDEG) g_csr[(size_t)d.w * MAXDEG + p3] = s.w;
    } else {
        for (; i < E; i++) {
            int d = dst[i];
            int p = atomicAdd(&g_deg[d], 1);
            if (p < MAXDEG) g_csr[(size_t)d * MAXDEG + p] = src[i];
        }
    }
}

// ---------------- GEMM + attention projections (templated) ----------------
template <int DIN, int L2OUT>
__global__ void __launch_bounds__(256) k_gemm_attn(
        const float* __restrict__ h_ext,
        const float* __restrict__ W,
        const float* __restrict__ al,
        const float* __restrict__ ar,
        int N) {
    constexpr int Q = DIN / 4;
    __shared__ float4 Wt4[Q * 32];
    __shared__ float4 hs4[8][4 * Q];
    __shared__ float sal[32], sar[32];

    const float* h = L2OUT ? g_out1 : h_ext;
    __half* featH = L2OUT ? g_feat2H : g_featH;
    float* elp = L2OUT ? g_el2 : g_el;
    float* erp = L2OUT ? g_er2 : g_er;

    int tid = threadIdx.x;
    for (int i = tid; i < Q * 32; i += 256) {
        int f = i / Q, q = i - f * Q;
        Wt4[q * 32 + f] = ((const float4*)W)[i];
    }
    if (tid < 32) { sal[tid] = al[tid]; sar[tid] = ar[tid]; }
    __syncthreads();

    int warp = tid >> 5, lane = tid & 31;
    int nbase = blockIdx.x * 32 + warp * 4;
    float4* hw = hs4[warp];

#pragma unroll
    for (int j = 0; j < 4; j++) {
        int n = nbase + j;
        if (n < N) {
            if (DIN == 128) {
                hw[j * Q + lane] = ((const float4*)(h + (size_t)n * DIN))[lane];
            } else {
                if (lane < Q)
                    hw[j * Q + lane] = ((const float4*)(h + (size_t)n * DIN))[lane];
            }
        }
    }
    __syncwarp();

    float acc[4] = {0.f, 0.f, 0.f, 0.f};
#pragma unroll 4
    for (int q = 0; q < Q; q++) {
        float4 w4 = Wt4[q * 32 + lane];
#pragma unroll
        for (int j = 0; j < 4; j++) {
            float4 h4 = hw[j * Q + q];
            acc[j] = fmaf(w4.x, h4.x, acc[j]);
            acc[j] = fmaf(w4.y, h4.y, acc[j]);
            acc[j] = fmaf(w4.z, h4.z, acc[j]);
            acc[j] = fmaf(w4.w, h4.w, acc[j]);
        }
    }

#pragma unroll
    for (int j = 0; j < 4; j++) {
        int n = nbase + j;
        if (n >= N) break;
        featH[(size_t)n * 32 + lane] = __float2half_rn(acc[j]);
        float vl = acc[j] * sal[lane];
        float vr = acc[j] * sar[lane];
#pragma unroll
        for (int o = 16; o; o >>= 1) {
            vl += __shfl_xor_sync(0xffffffffu, vl, o);
            vr += __shfl_xor_sync(0xffffffffu, vr, o);
        }
        if (lane == 0) { elp[n] = vl; erp[n] = vr; }
    }
}

// ---- half-warp-per-node aggregate core -------------------------------------
// Each 16-lane half handles one node. Phase 1: lane16 = edge (16 edges/iter).
// Phase 2: 4 edge-groups (g4) x 4 feature-lanes (r4); uint4 = 8 halfs per lane.
// CRITICAL: the two halves have different cnt and diverge on trip count, so
// every shuffle uses the SEGMENT mask (0xffff << 16*half) with width 16 —
// lanes within a half are always converged with each other.
__device__ __forceinline__ void edge_loop16(
        const int* __restrict__ csr, int cnt,
        const float* __restrict__ el, const uint4* __restrict__ feat16,
        float ern, unsigned smask, int lane16, int g4, int r4,
        float& ssum, float4& aLo, float4& aHi) {
    for (int j0 = 0; j0 < cnt; j0 += 16) {
        int j = j0 + lane16;
        bool v = j < cnt;
        int s = csr[v ? j : 0];
        float e = el[s] + ern;
        e = (e >= 0.f) ? e : NEG_SLOPE * e;
        float w = v ? __expf(e) : 0.f;
        ssum += w;
        int kmax = cnt - j0; if (kmax > 16) kmax = 16;
        for (int k = 0; k < kmax; k += 4) {
            int srcl = k + g4;
            int   sk = __shfl_sync(smask, s, srcl, 16);
            float wk = __shfl_sync(smask, w, srcl, 16);
            uint4 p = feat16[(size_t)sk * 4 + r4];   // 8 halfs (16B of 64B row)
            float2 f0 = __half22float2(*(__half2*)&p.x);
            float2 f1 = __half22float2(*(__half2*)&p.y);
            float2 f2 = __half22float2(*(__half2*)&p.z);
            float2 f3 = __half22float2(*(__half2*)&p.w);
            aLo.x = fmaf(wk, f0.x, aLo.x); aLo.y = fmaf(wk, f0.y, aLo.y);
            aLo.z = fmaf(wk, f1.x, aLo.z); aLo.w = fmaf(wk, f1.y, aLo.w);
            aHi.x = fmaf(wk, f2.x, aHi.x); aHi.y = fmaf(wk, f2.y, aHi.y);
            aHi.z = fmaf(wk, f3.x, aHi.z); aHi.w = fmaf(wk, f3.y, aHi.w);
        }
    }
    // reductions: also segment-masked (halves may be diverged from each other)
#pragma unroll
    for (int o = 8; o; o >>= 1) ssum += __shfl_xor_sync(smask, ssum, o, 16);
#pragma unroll
    for (int o = 4; o <= 8; o <<= 1) {
        aLo.x += __shfl_xor_sync(smask, aLo.x, o, 16);
        aLo.y += __shfl_xor_sync(smask, aLo.y, o, 16);
        aLo.z += __shfl_xor_sync(smask, aLo.z, o, 16);
        aLo.w += __shfl_xor_sync(smask, aLo.w, o, 16);
        aHi.x += __shfl_xor_sync(smask, aHi.x, o, 16);
        aHi.y += __shfl_xor_sync(smask, aHi.y, o, 16);
        aHi.z += __shfl_xor_sync(smask, aHi.z, o, 16);
        aHi.w += __shfl_xor_sync(smask, aHi.w, o, 16);
    }
}

// Generic aggregate: el/feat/er in, float4 out rows. 2 nodes per warp.
__device__ __forceinline__ void agg_body(
        const float* __restrict__ el, const float* __restrict__ er,
        const uint4* __restrict__ feat16, const float* __restrict__ bias,
        float4* __restrict__ out4, int N) {
    int tid = threadIdx.x;
    int lane = tid & 31;
    int half = lane >> 4, lane16 = lane & 15;
    int g4 = lane16 >> 2, r4 = lane16 & 3;
    unsigned smask = 0xffffu << (half << 4);
    int n = ((blockIdx.x * blockDim.x + tid) >> 5) * 2 + half;

    int nn = (n < N) ? n : (N - 1);     // safe pointer for inactive halves
    int cnt = (n < N) ? g_deg[nn] : 0;
    if (cnt > MAXDEG) cnt = MAXDEG;

    float ssum = 0.f;
    float4 aLo = {0.f, 0.f, 0.f, 0.f}, aHi = {0.f, 0.f, 0.f, 0.f};
    edge_loop16(g_csr + (size_t)nn * MAXDEG, cnt, el, feat16, er[nn],
                smask, lane16, g4, r4, ssum, aLo, aHi);

    if (n < N && g4 == 0) {
        float4 bLo = ((const float4*)bias)[2 * r4];
        float4 bHi = ((const float4*)bias)[2 * r4 + 1];
        float inv = (cnt > 0) ? (1.f / ssum) : 0.f;
        float4 oLo, oHi;
        oLo.x = fmaf(aLo.x, inv, bLo.x); oLo.y = fmaf(aLo.y, inv, bLo.y);
        oLo.z = fmaf(aLo.z, inv, bLo.z); oLo.w = fmaf(aLo.w, inv, bLo.w);
        oHi.x = fmaf(aHi.x, inv, bHi.x); oHi.y = fmaf(aHi.y, inv, bHi.y);
        oHi.z = fmaf(aHi.z, inv, bHi.z); oHi.w = fmaf(aHi.w, inv, bHi.w);
        out4[(size_t)n * 8 + 2 * r4]     = oLo;
        out4[(size_t)n * 8 + 2 * r4 + 1] = oHi;
    }
}

__global__ void __launch_bounds__(256) k_agg1(const float* __restrict__ b1, int N) {
    agg_body(g_el, g_er, (const uint4*)g_featH, b1, (float4*)g_out1, N);
}

__global__ void __launch_bounds__(256) k_agg2(const float* __restrict__ b2,
                                              float* __restrict__ out, int N) {
    agg_body(g_el2, g_er2, (const uint4*)g_feat2H, b2, (float4*)out, N);
}

// ---------------- driver ----------------
extern "C" void kernel_launch(void* const* d_in, const int* in_sizes, int n_in,
                              void* d_out, int out_size) {
    const float* features = (const float*)d_in[0];
    const int*   src      = (const int*)d_in[1];
    const int*   dst      = (const int*)d_in[2];
    const float* W1  = (const float*)d_in[3];
    const float* al1 = (const float*)d_in[4];
    const float* ar1 = (const float*)d_in[5];
    const float* b1  = (const float*)d_in[6];
    const float* W2  = (const float*)d_in[7];
    const float* al2 = (const float*)d_in[8];
    const float* ar2 = (const float*)d_in[9];
    const float* b2  = (const float*)d_in[10];

    int E = in_sizes[1];
    int N = in_sizes[0] / 128;
    if (N > NN) N = NN;
    if (E > EE) E = EE;

    float* out = (float*)d_out;

    static cudaStream_t s_side = nullptr;
    static cudaEvent_t ev_fork = nullptr, ev_join = nullptr;
    if (!s_side) {
        cudaStreamCreateWithFlags(&s_side, cudaStreamNonBlocking);
        cudaEventCreateWithFlags(&ev_fork, cudaEventDisableTiming);
        cudaEventCreateWithFlags(&ev_join, cudaEventDisableTiming);
    }

    const int T = 256;
    int gN = (N + T - 1) / T;
    int gE4 = (E / 4 + T) / T + 1;
    int gGemm = (N + 31) / 32;
    int gAgg = (N + 15) / 16;      // 8 warps x 2 nodes per 256-thread block

    // fork: GEMM1 runs concurrently with CSR build
    cudaEventRecord(ev_fork, 0);
    cudaStreamWaitEvent(s_side, ev_fork, 0);
    k_gemm_attn<128, 0><<<gGemm, T, 0, s_side>>>(features, W1, al1, ar1, N);
    cudaEventRecord(ev_join, s_side);

    k_zero<<<gN, T>>>(N);
    k_scatter<<<gE4, T>>>(src, dst, E);

    cudaStreamWaitEvent(0, ev_join, 0);

    // layer 1 aggregate -> fp32 out1
    k_agg1<<<gAgg, T>>>(b1, N);
    // GEMM2 + layer-2 projections (register-blocked, 4 nodes/warp)
    k_gemm_attn<32, 1><<<gGemm, T>>>(nullptr, W2, al2, ar2, N);
    // layer 2 aggregate -> final output
    k_agg2<<<gAgg, T>>>(b2, out, N);
}

// round 13
// speedup vs baseline: 1.3108x; 1.0532x over previous
#include <cuda_runtime.h>
#include <cuda_fp16.h>

#define NN 100000
#define EE 1600000
#define MAXDEG 128
#define NEG_SLOPE 0.2f

// ---------------- scratch (static device globals; no allocation) ----------------
__device__ int    g_deg[NN];
__device__ int    g_csr[(size_t)NN * MAXDEG];   // padded CSR: src list per dst
__device__ __half g_featH[(size_t)NN * 32];     // layer-1 features (fp16, 64B rows)
__device__ float  g_el[NN], g_er[NN];
__device__ float  g_out1[(size_t)NN * 32];      // layer-1 output (fp32)
__device__ __half g_feat2H[(size_t)NN * 32];    // layer-2 features (fp16)
__device__ float  g_el2[NN], g_er2[NN];

// ---------------- build: zero degrees, then direct scatter ----------------
__global__ void k_zero(int N) {
    int i = blockIdx.x * blockDim.x + threadIdx.x;
    if (i < N) g_deg[i] = 0;
}

__global__ void k_scatter(const int* __restrict__ src, const int* __restrict__ dst, int E) {
    int i = (blockIdx.x * blockDim.x + threadIdx.x) * 4;
    if (i + 3 < E) {
        int4 s = *(const int4*)(src + i);
        int4 d = *(const int4*)(dst + i);
        int p0 = atomicAdd(&g_deg[d.x], 1);
        int p1 = atomicAdd(&g_deg[d.y], 1);
        int p2 = atomicAdd(&g_deg[d.z], 1);
        int p3 = atomicAdd(&g_deg[d.w], 1);
        if (p0 < MAXDEG) g_csr[(size_t)d.x * MAXDEG + p0] = s.x;
        if (p1 < MAXDEG) g_csr[(size_t)d.y * MAXDEG + p1] = s.y;
        if (p2 < MAXDEG) g_csr[(size_t)d.z * MAXDEG + p2] = s.z;
        if (p3 < MAXDEG) g_csr[(size_t)d.w * MAXDEG + p3] = s.w;
    } else {
        for (; i < E; i++) {
            int d = dst[i];
            int p = atomicAdd(&g_deg[d], 1);
            if (p < MAXDEG) g_csr[(size_t)d * MAXDEG + p] = src[i];
        }
    }
}

// ---------------- GEMM + attention projections (templated) ----------------
template <int DIN, int L2OUT>
__global__ void __launch_bounds__(256) k_gemm_attn(
        const float* __restrict__ h_ext,
        const float* __restrict__ W,
        const float* __restrict__ al,
        const float* __restrict__ ar,
        int N) {
    constexpr int Q = DIN / 4;
    __shared__ float4 Wt4[Q * 32];
    __shared__ float4 hs4[8][4 * Q];
    __shared__ float sal[32], sar[32];

    const float* h = L2OUT ? g_out1 : h_ext;
    __half* featH = L2OUT ? g_feat2H : g_featH;
    float* elp = L2OUT ? g_el2 : g_el;
    float* erp = L2OUT ? g_er2 : g_er;

    int tid = threadIdx.x;
    for (int i = tid; i < Q * 32; i += 256) {
        int f = i / Q, q = i - f * Q;
        Wt4[q * 32 + f] = ((const float4*)W)[i];
    }
    if (tid < 32) { sal[tid] = al[tid]; sar[tid] = ar[tid]; }
    __syncthreads();

    int warp = tid >> 5, lane = tid & 31;
    int nbase = blockIdx.x * 32 + warp * 4;
    float4* hw = hs4[warp];

#pragma unroll
    for (int j = 0; j < 4; j++) {
        int n = nbase + j;
        if (n < N) {
            if (DIN == 128) {
                hw[j * Q + lane] = ((const float4*)(h + (size_t)n * DIN))[lane];
            } else {
                if (lane < Q)
                    hw[j * Q + lane] = ((const float4*)(h + (size_t)n * DIN))[lane];
            }
        }
    }
    __syncwarp();

    float acc[4] = {0.f, 0.f, 0.f, 0.f};
#pragma unroll 4
    for (int q = 0; q < Q; q++) {
        float4 w4 = Wt4[q * 32 + lane];
#pragma unroll
        for (int j = 0; j < 4; j++) {
            float4 h4 = hw[j * Q + q];
            acc[j] = fmaf(w4.x, h4.x, acc[j]);
            acc[j] = fmaf(w4.y, h4.y, acc[j]);
            acc[j] = fmaf(w4.z, h4.z, acc[j]);
            acc[j] = fmaf(w4.w, h4.w, acc[j]);
        }
    }

#pragma unroll
    for (int j = 0; j < 4; j++) {
        int n = nbase + j;
        if (n >= N) break;
        featH[(size_t)n * 32 + lane] = __float2half_rn(acc[j]);
        float vl = acc[j] * sal[lane];
        float vr = acc[j] * sar[lane];
#pragma unroll
        for (int o = 16; o; o >>= 1) {
            vl += __shfl_xor_sync(0xffffffffu, vl, o);
            vr += __shfl_xor_sync(0xffffffffu, vr, o);
        }
        if (lane == 0) { elp[n] = vl; erp[n] = vr; }
    }
}

// ---- 8-lane-segment-per-node aggregate core --------------------------------
// Each 8-lane segment handles one node (4 nodes/warp).
// Phase 1: lane8 = edge (8 edges per block, w=0 padding for tails).
// Phase 2: 2 edge-groups (g2) x 4 feature-lanes (r4); uint4 = 8 halfs/lane.
// Segments diverge on trip count -> all shuffles use the SEGMENT mask
// (0xff << 8*quarter) with width 8.
__device__ __forceinline__ void edge_loop8(
        const int* __restrict__ csr, int cnt,
        const float* __restrict__ el, const uint4* __restrict__ feat16,
        float ern, unsigned smask, int lane8, int g2, int r4,
        float& ssum, float4& aLo, float4& aHi) {
    for (int j0 = 0; j0 < cnt; j0 += 8) {
        // phase 1: this lane's edge
        int j = j0 + lane8;
        bool v = j < cnt;
        int s = csr[v ? j : 0];
        float e = el[s] + ern;
        e = (e >= 0.f) ? e : NEG_SLOPE * e;
        float w = v ? __expf(e) : 0.f;
        ssum += w;
        // phase 2: 8 edges = 4 chunk-steps x 2 groups, fully unrolled,
        // all 4 gathers issued before the FMA chains (w=0 pads are free).
        int   sk0 = __shfl_sync(smask, s, 0 + g2, 8);
        float wk0 = __shfl_sync(smask, w, 0 + g2, 8);
        int   sk1 = __shfl_sync(smask, s, 2 + g2, 8);
        float wk1 = __shfl_sync(smask, w, 2 + g2, 8);
        int   sk2 = __shfl_sync(smask, s, 4 + g2, 8);
        float wk2 = __shfl_sync(smask, w, 4 + g2, 8);
        int   sk3 = __shfl_sync(smask, s, 6 + g2, 8);
        float wk3 = __shfl_sync(smask, w, 6 + g2, 8);
        uint4 p0 = feat16[(size_t)sk0 * 4 + r4];
        uint4 p1 = feat16[(size_t)sk1 * 4 + r4];
        uint4 p2 = feat16[(size_t)sk2 * 4 + r4];
        uint4 p3 = feat16[(size_t)sk3 * 4 + r4];
        float2 f;
        f = __half22float2(*(__half2*)&p0.x); aLo.x = fmaf(wk0, f.x, aLo.x); aLo.y = fmaf(wk0, f.y, aLo.y);
        f = __half22float2(*(__half2*)&p0.y); aLo.z = fmaf(wk0, f.x, aLo.z); aLo.w = fmaf(wk0, f.y, aLo.w);
        f = __half22float2(*(__half2*)&p0.z); aHi.x = fmaf(wk0, f.x, aHi.x); aHi.y = fmaf(wk0, f.y, aHi.y);
        f = __half22float2(*(__half2*)&p0.w); aHi.z = fmaf(wk0, f.x, aHi.z); aHi.w = fmaf(wk0, f.y, aHi.w);
        f = __half22float2(*(__half2*)&p1.x); aLo.x = fmaf(wk1, f.x, aLo.x); aLo.y = fmaf(wk1, f.y, aLo.y);
        f = __half22float2(*(__half2*)&p1.y); aLo.z = fmaf(wk1, f.x, aLo.z); aLo.w = fmaf(wk1, f.y, aLo.w);
        f = __half22float2(*(__half2*)&p1.z); aHi.x = fmaf(wk1, f.x, aHi.x); aHi.y = fmaf(wk1, f.y, aHi.y);
        f = __half22float2(*(__half2*)&p1.w); aHi.z = fmaf(wk1, f.x, aHi.z); aHi.w = fmaf(wk1, f.y, aHi.w);
        f = __half22float2(*(__half2*)&p2.x); aLo.x = fmaf(wk2, f.x, aLo.x); aLo.y = fmaf(wk2, f.y, aLo.y);
        f = __half22float2(*(__half2*)&p2.y); aLo.z = fmaf(wk2, f.x, aLo.z); aLo.w = fmaf(wk2, f.y, aLo.w);
        f = __half22float2(*(__half2*)&p2.z); aHi.x = fmaf(wk2, f.x, aHi.x); aHi.y = fmaf(wk2, f.y, aHi.y);
        f = __half22float2(*(__half2*)&p2.w); aHi.z = fmaf(wk2, f.x, aHi.z); aHi.w = fmaf(wk2, f.y, aHi.w);
        f = __half22float2(*(__half2*)&p3.x); aLo.x = fmaf(wk3, f.x, aLo.x); aLo.y = fmaf(wk3, f.y, aLo.y);
        f = __half22float2(*(__half2*)&p3.y); aLo.z = fmaf(wk3, f.x, aLo.z); aLo.w = fmaf(wk3, f.y, aLo.w);
        f = __half22float2(*(__half2*)&p3.z); aHi.x = fmaf(wk3, f.x, aHi.x); aHi.y = fmaf(wk3, f.y, aHi.y);
        f = __half22float2(*(__half2*)&p3.w); aHi.z = fmaf(wk3, f.x, aHi.z); aHi.w = fmaf(wk3, f.y, aHi.w);
    }
    // reductions (segment-masked): ssum over 8 lanes, acc over 2 groups
#pragma unroll
    for (int o = 4; o; o >>= 1) ssum += __shfl_xor_sync(smask, ssum, o, 8);
    aLo.x += __shfl_xor_sync(smask, aLo.x, 4, 8);
    aLo.y += __shfl_xor_sync(smask, aLo.y, 4, 8);
    aLo.z += __shfl_xor_sync(smask, aLo.z, 4, 8);
    aLo.w += __shfl_xor_sync(smask, aLo.w, 4, 8);
    aHi.x += __shfl_xor_sync(smask, aHi.x, 4, 8);
    aHi.y += __shfl_xor_sync(smask, aHi.y, 4, 8);
    aHi.z += __shfl_xor_sync(smask, aHi.z, 4, 8);
    aHi.w += __shfl_xor_sync(smask, aHi.w, 4, 8);
}

// Generic aggregate: 4 nodes per warp (8-lane segments).
__device__ __forceinline__ void agg_body(
        const float* __restrict__ el, const float* __restrict__ er,
        const uint4* __restrict__ feat16, const float* __restrict__ bias,
        float4* __restrict__ out4, int N) {
    int tid = threadIdx.x;
    int lane = tid & 31;
    int quarter = lane >> 3, lane8 = lane & 7;
    int g2 = lane8 >> 2, r4 = lane8 & 3;
    unsigned smask = 0xffu << (quarter << 3);
    int n = ((blockIdx.x * blockDim.x + tid) >> 5) * 4 + quarter;

    int nn = (n < N) ? n : (N - 1);     // safe pointer for inactive segments
    int cnt = (n < N) ? g_deg[nn] : 0;
    if (cnt > MAXDEG) cnt = MAXDEG;

    float ssum = 0.f;
    float4 aLo = {0.f, 0.f, 0.f, 0.f}, aHi = {0.f, 0.f, 0.f, 0.f};
    edge_loop8(g_csr + (size_t)nn * MAXDEG, cnt, el, feat16, er[nn],
               smask, lane8, g2, r4, ssum, aLo, aHi);

    if (n < N && g2 == 0) {
        float4 bLo = ((const float4*)bias)[2 * r4];
        float4 bHi = ((const float4*)bias)[2 * r4 + 1];
        float inv = (cnt > 0) ? (1.f / ssum) : 0.f;
        float4 oLo, oHi;
        oLo.x = fmaf(aLo.x, inv, bLo.x); oLo.y = fmaf(aLo.y, inv, bLo.y);
        oLo.z = fmaf(aLo.z, inv, bLo.z); oLo.w = fmaf(aLo.w, inv, bLo.w);
        oHi.x = fmaf(aHi.x, inv, bHi.x); oHi.y = fmaf(aHi.y, inv, bHi.y);
        oHi.z = fmaf(aHi.z, inv, bHi.z); oHi.w = fmaf(aHi.w, inv, bHi.w);
        out4[(size_t)n * 8 + 2 * r4]     = oLo;
        out4[(size_t)n * 8 + 2 * r4 + 1] = oHi;
    }
}

__global__ void __launch_bounds__(256) k_agg1(const float* __restrict__ b1, int N) {
    agg_body(g_el, g_er, (const uint4*)g_featH, b1, (float4*)g_out1, N);
}

__global__ void __launch_bounds__(256) k_agg2(const float* __restrict__ b2,
                                              float* __restrict__ out, int N) {
    agg_body(g_el2, g_er2, (const uint4*)g_feat2H, b2, (float4*)out, N);
}

// ---------------- driver ----------------
extern "C" void kernel_launch(void* const* d_in, const int* in_sizes, int n_in,
                              void* d_out, int out_size) {
    const float* features = (const float*)d_in[0];
    const int*   src      = (const int*)d_in[1];
    const int*   dst      = (const int*)d_in[2];
    const float* W1  = (const float*)d_in[3];
    const float* al1 = (const float*)d_in[4];
    const float* ar1 = (const float*)d_in[5];
    const float* b1  = (const float*)d_in[6];
    const float* W2  = (const float*)d_in[7];
    const float* al2 = (const float*)d_in[8];
    const float* ar2 = (const float*)d_in[9];
    const float* b2  = (const float*)d_in[10];

    int E = in_sizes[1];
    int N = in_sizes[0] / 128;
    if (N > NN) N = NN;
    if (E > EE) E = EE;

    float* out = (float*)d_out;

    static cudaStream_t s_side = nullptr;
    static cudaEvent_t ev_fork = nullptr, ev_join = nullptr;
    if (!s_side) {
        cudaStreamCreateWithFlags(&s_side, cudaStreamNonBlocking);
        cudaEventCreateWithFlags(&ev_fork, cudaEventDisableTiming);
        cudaEventCreateWithFlags(&ev_join, cudaEventDisableTiming);
    }

    const int T = 256;
    int gN = (N + T - 1) / T;
    int gE4 = (E / 4 + T) / T + 1;
    int gGemm = (N + 31) / 32;
    int gAgg = (N + 31) / 32;      // 8 warps x 4 nodes per 256-thread block

    // fork: GEMM1 runs concurrently with CSR build
    cudaEventRecord(ev_fork, 0);
    cudaStreamWaitEvent(s_side, ev_fork, 0);
    k_gemm_attn<128, 0><<<gGemm, T, 0, s_side>>>(features, W1, al1, ar1, N);
    cudaEventRecord(ev_join, s_side);

    k_zero<<<gN, T>>>(N);
    k_scatter<<<gE4, T>>>(src, dst, E);

    cudaStreamWaitEvent(0, ev_join, 0);

    // layer 1 aggregate -> fp32 out1
    k_agg1<<<gAgg, T>>>(b1, N);
    // GEMM2 + layer-2 projections (register-blocked, 4 nodes/warp)
    k_gemm_attn<32, 1><<<gGemm, T>>>(nullptr, W2, al2, ar2, N);
    // layer 2 aggregate -> final output
    k_agg2<<<gAgg, T>>>(b2, out, N);
}

// round 14
// speedup vs baseline: 1.3673x; 1.0431x over previous
#include <cuda_runtime.h>
#include <cuda_fp16.h>

#define NN 100000
#define EE 1600000
#define MAXDEG 128
#define NEG_SLOPE 0.2f

// ---------------- scratch (static device globals; no allocation) ----------------
__device__ int    g_deg[NN];
__device__ int    g_csr[(size_t)NN * MAXDEG];   // padded CSR: src list per dst
__device__ __half g_featH[(size_t)NN * 32];     // layer-1 features (fp16, 64B rows)
__device__ float  g_el[NN], g_er[NN];
__device__ __half g_feat2H[(size_t)NN * 32];    // layer-2 features (fp16)
__device__ float  g_el2[NN], g_er2[NN];

// ---------------- build: zero degrees, then direct scatter ----------------
__global__ void k_zero(int N) {
    int i = blockIdx.x * blockDim.x + threadIdx.x;
    if (i < N) g_deg[i] = 0;
}

__global__ void k_scatter(const int* __restrict__ src, const int* __restrict__ dst, int E) {
    int i = (blockIdx.x * blockDim.x + threadIdx.x) * 4;
    if (i + 3 < E) {
        int4 s = *(const int4*)(src + i);
        int4 d = *(const int4*)(dst + i);
        int p0 = atomicAdd(&g_deg[d.x], 1);
        int p1 = atomicAdd(&g_deg[d.y], 1);
        int p2 = atomicAdd(&g_deg[d.z], 1);
        int p3 = atomicAdd(&g_deg[d.w], 1);
        if (p0 < MAXDEG) g_csr[(size_t)d.x * MAXDEG + p0] = s.x;
        if (p1 < MAXDEG) g_csr[(size_t)d.y * MAXDEG + p1] = s.y;
        if (p2 < MAXDEG) g_csr[(size_t)d.z * MAXDEG + p2] = s.z;
        if (p3 < MAXDEG) g_csr[(size_t)d.w * MAXDEG + p3] = s.w;
    } else {
        for (; i < E; i++) {
            int d = dst[i];
            int p = atomicAdd(&g_deg[d], 1);
            if (p < MAXDEG) g_csr[(size_t)d * MAXDEG + p] = src[i];
        }
    }
}

// ---------------- GEMM1 + attention projections (DIN=128) ----------------
__global__ void __launch_bounds__(256) k_gemm_attn1(
        const float* __restrict__ h,
        const float* __restrict__ W,
        const float* __restrict__ al,
        const float* __restrict__ ar,
        int N) {
    constexpr int Q = 32;
    __shared__ float4 Wt4[Q * 32];
    __shared__ float4 hs4[8][4 * Q];
    __shared__ float sal[32], sar[32];

    int tid = threadIdx.x;
    for (int i = tid; i < Q * 32; i += 256) {
        int f = i / Q, q = i - f * Q;
        Wt4[q * 32 + f] = ((const float4*)W)[i];
    }
    if (tid < 32) { sal[tid] = al[tid]; sar[tid] = ar[tid]; }
    __syncthreads();

    int warp = tid >> 5, lane = tid & 31;
    int nbase = blockIdx.x * 32 + warp * 4;
    float4* hw = hs4[warp];

#pragma unroll
    for (int j = 0; j < 4; j++) {
        int n = nbase + j;
        if (n < N) hw[j * Q + lane] = ((const float4*)(h + (size_t)n * 128))[lane];
    }
    __syncwarp();

    float acc[4] = {0.f, 0.f, 0.f, 0.f};
#pragma unroll 4
    for (int q = 0; q < Q; q++) {
        float4 w4 = Wt4[q * 32 + lane];
#pragma unroll
        for (int j = 0; j < 4; j++) {
            float4 h4 = hw[j * Q + q];
            acc[j] = fmaf(w4.x, h4.x, acc[j]);
            acc[j] = fmaf(w4.y, h4.y, acc[j]);
            acc[j] = fmaf(w4.z, h4.z, acc[j]);
            acc[j] = fmaf(w4.w, h4.w, acc[j]);
        }
    }

#pragma unroll
    for (int j = 0; j < 4; j++) {
        int n = nbase + j;
        if (n >= N) break;
        g_featH[(size_t)n * 32 + lane] = __float2half_rn(acc[j]);
        float vl = acc[j] * sal[lane];
        float vr = acc[j] * sar[lane];
#pragma unroll
        for (int o = 16; o; o >>= 1) {
            vl += __shfl_xor_sync(0xffffffffu, vl, o);
            vr += __shfl_xor_sync(0xffffffffu, vr, o);
        }
        if (lane == 0) { g_el[n] = vl; g_er[n] = vr; }
    }
}

// ---- 8-lane-segment-per-node aggregate core (4 nodes/warp) -----------------
// Segment-masked shuffles (segments diverge on trip count).
__device__ __forceinline__ void edge_loop8(
        const int* __restrict__ csr, int cnt,
        const float* __restrict__ el, const uint4* __restrict__ feat16,
        float ern, unsigned smask, int lane8, int g2, int r4,
        float& ssum, float4& aLo, float4& aHi) {
    for (int j0 = 0; j0 < cnt; j0 += 8) {
        int j = j0 + lane8;
        bool v = j < cnt;
        int s = csr[v ? j : 0];
        float e = el[s] + ern;
        e = (e >= 0.f) ? e : NEG_SLOPE * e;
        float w = v ? __expf(e) : 0.f;
        ssum += w;
        int   sk0 = __shfl_sync(smask, s, 0 + g2, 8);
        float wk0 = __shfl_sync(smask, w, 0 + g2, 8);
        int   sk1 = __shfl_sync(smask, s, 2 + g2, 8);
        float wk1 = __shfl_sync(smask, w, 2 + g2, 8);
        int   sk2 = __shfl_sync(smask, s, 4 + g2, 8);
        float wk2 = __shfl_sync(smask, w, 4 + g2, 8);
        int   sk3 = __shfl_sync(smask, s, 6 + g2, 8);
        float wk3 = __shfl_sync(smask, w, 6 + g2, 8);
        uint4 p0 = feat16[(size_t)sk0 * 4 + r4];
        uint4 p1 = feat16[(size_t)sk1 * 4 + r4];
        uint4 p2 = feat16[(size_t)sk2 * 4 + r4];
        uint4 p3 = feat16[(size_t)sk3 * 4 + r4];
        float2 f;
        f = __half22float2(*(__half2*)&p0.x); aLo.x = fmaf(wk0, f.x, aLo.x); aLo.y = fmaf(wk0, f.y, aLo.y);
        f = __half22float2(*(__half2*)&p0.y); aLo.z = fmaf(wk0, f.x, aLo.z); aLo.w = fmaf(wk0, f.y, aLo.w);
        f = __half22float2(*(__half2*)&p0.z); aHi.x = fmaf(wk0, f.x, aHi.x); aHi.y = fmaf(wk0, f.y, aHi.y);
        f = __half22float2(*(__half2*)&p0.w); aHi.z = fmaf(wk0, f.x, aHi.z); aHi.w = fmaf(wk0, f.y, aHi.w);
        f = __half22float2(*(__half2*)&p1.x); aLo.x = fmaf(wk1, f.x, aLo.x); aLo.y = fmaf(wk1, f.y, aLo.y);
        f = __half22float2(*(__half2*)&p1.y); aLo.z = fmaf(wk1, f.x, aLo.z); aLo.w = fmaf(wk1, f.y, aLo.w);
        f = __half22float2(*(__half2*)&p1.z); aHi.x = fmaf(wk1, f.x, aHi.x); aHi.y = fmaf(wk1, f.y, aHi.y);
        f = __half22float2(*(__half2*)&p1.w); aHi.z = fmaf(wk1, f.x, aHi.z); aHi.w = fmaf(wk1, f.y, aHi.w);
        f = __half22float2(*(__half2*)&p2.x); aLo.x = fmaf(wk2, f.x, aLo.x); aLo.y = fmaf(wk2, f.y, aLo.y);
        f = __half22float2(*(__half2*)&p2.y); aLo.z = fmaf(wk2, f.x, aLo.z); aLo.w = fmaf(wk2, f.y, aLo.w);
        f = __half22float2(*(__half2*)&p2.z); aHi.x = fmaf(wk2, f.x, aHi.x); aHi.y = fmaf(wk2, f.y, aHi.y);
        f = __half22float2(*(__half2*)&p2.w); aHi.z = fmaf(wk2, f.x, aHi.z); aHi.w = fmaf(wk2, f.y, aHi.w);
        f = __half22float2(*(__half2*)&p3.x); aLo.x = fmaf(wk3, f.x, aLo.x); aLo.y = fmaf(wk3, f.y, aLo.y);
        f = __half22float2(*(__half2*)&p3.y); aLo.z = fmaf(wk3, f.x, aLo.z); aLo.w = fmaf(wk3, f.y, aLo.w);
        f = __half22float2(*(__half2*)&p3.z); aHi.x = fmaf(wk3, f.x, aHi.x); aHi.y = fmaf(wk3, f.y, aHi.y);
        f = __half22float2(*(__half2*)&p3.w); aHi.z = fmaf(wk3, f.x, aHi.z); aHi.w = fmaf(wk3, f.y, aHi.w);
    }
#pragma unroll
    for (int o = 4; o; o >>= 1) ssum += __shfl_xor_sync(smask, ssum, o, 8);
    aLo.x += __shfl_xor_sync(smask, aLo.x, 4, 8);
    aLo.y += __shfl_xor_sync(smask, aLo.y, 4, 8);
    aLo.z += __shfl_xor_sync(smask, aLo.z, 4, 8);
    aLo.w += __shfl_xor_sync(smask, aLo.w, 4, 8);
    aHi.x += __shfl_xor_sync(smask, aHi.x, 4, 8);
    aHi.y += __shfl_xor_sync(smask, aHi.y, 4, 8);
    aHi.z += __shfl_xor_sync(smask, aHi.z, 4, 8);
    aHi.w += __shfl_xor_sync(smask, aHi.w, 4, 8);
}

// ---------------- fused: agg1 (4 nodes/warp) + GEMM2 + layer-2 projections --
// Block = 8 warps x 4 nodes = 32 nodes. Layer-1 rows go to shared rowbuf
// (never to global); after __syncwarp each warp runs the register-blocked
// GEMM2 for its own 4 nodes (same tiling as the old standalone kernel).
__global__ void __launch_bounds__(256) k_agg1_gemm2(
        const float* __restrict__ b1,
        const float* __restrict__ W2,
        const float* __restrict__ al2,
        const float* __restrict__ ar2,
        int N) {
    __shared__ float4 W2t4[8 * 32];          // W2t4[q*32+f] = W2[f][4q..4q+3]
    __shared__ float sal[32], sar[32];
    __shared__ __align__(16) float rowbuf[32][32];   // [local node][feature]

    int tid = threadIdx.x;
    for (int i = tid; i < 8 * 32; i += 256) {
        int f = i / 8, q = i - f * 8;
        W2t4[q * 32 + f] = ((const float4*)W2)[i];
    }
    if (tid < 32) { sal[tid] = al2[tid]; sar[tid] = ar2[tid]; }
    __syncthreads();

    int lane = tid & 31;
    int warp = tid >> 5;
    int quarter = lane >> 3, lane8 = lane & 7;
    int g2 = lane8 >> 2, r4 = lane8 & 3;
    unsigned smask = 0xffu << (quarter << 3);
    int local = warp * 4 + quarter;
    int n = blockIdx.x * 32 + local;

    int nn = (n < N) ? n : (N - 1);
    int cnt = (n < N) ? g_deg[nn] : 0;
    if (cnt > MAXDEG) cnt = MAXDEG;

    float ssum = 0.f;
    float4 aLo = {0.f, 0.f, 0.f, 0.f}, aHi = {0.f, 0.f, 0.f, 0.f};
    edge_loop8(g_csr + (size_t)nn * MAXDEG, cnt, g_el,
               (const uint4*)g_featH, g_er[nn],
               smask, lane8, g2, r4, ssum, aLo, aHi);

    // layer-1 row -> shared (g2==0 lanes hold the reduced values)
    if (g2 == 0) {
        float4 bLo = ((const float4*)b1)[2 * r4];
        float4 bHi = ((const float4*)b1)[2 * r4 + 1];
        float inv = (cnt > 0) ? (1.f / ssum) : 0.f;
        float4 oLo, oHi;
        oLo.x = fmaf(aLo.x, inv, bLo.x); oLo.y = fmaf(aLo.y, inv, bLo.y);
        oLo.z = fmaf(aLo.z, inv, bLo.z); oLo.w = fmaf(aLo.w, inv, bLo.w);
        oHi.x = fmaf(aHi.x, inv, bHi.x); oHi.y = fmaf(aHi.y, inv, bHi.y);
        oHi.z = fmaf(aHi.z, inv, bHi.z); oHi.w = fmaf(aHi.w, inv, bHi.w);
        float4* row4 = (float4*)rowbuf[local];
        row4[2 * r4]     = oLo;
        row4[2 * r4 + 1] = oHi;
    }
    __syncwarp();   // warp's 4 segments wrote the warp's 4 rows

    // GEMM2 for this warp's 4 nodes: lane = output feature
    int nbase = blockIdx.x * 32 + warp * 4;
    float acc[4] = {0.f, 0.f, 0.f, 0.f};
#pragma unroll
    for (int q = 0; q < 8; q++) {
        float4 w4 = W2t4[q * 32 + lane];
#pragma unroll
        for (int j = 0; j < 4; j++) {
            float4 h4 = ((const float4*)rowbuf[warp * 4 + j])[q];
            acc[j] = fmaf(w4.x, h4.x, acc[j]);
            acc[j] = fmaf(w4.y, h4.y, acc[j]);
            acc[j] = fmaf(w4.z, h4.z, acc[j]);
            acc[j] = fmaf(w4.w, h4.w, acc[j]);
        }
    }

#pragma unroll
    for (int j = 0; j < 4; j++) {
        int nj = nbase + j;
        if (nj >= N) break;
        g_feat2H[(size_t)nj * 32 + lane] = __float2half_rn(acc[j]);
        float vl = acc[j] * sal[lane];
        float vr = acc[j] * sar[lane];
#pragma unroll
        for (int o = 16; o; o >>= 1) {
            vl += __shfl_xor_sync(0xffffffffu, vl, o);
            vr += __shfl_xor_sync(0xffffffffu, vr, o);
        }
        if (lane == 0) { g_el2[nj] = vl; g_er2[nj] = vr; }
    }
}

// ---------------- final aggregate (layer 2) ----------------
__global__ void __launch_bounds__(256) k_agg2(const float* __restrict__ b2,
                                              float* __restrict__ out, int N) {
    int tid = threadIdx.x;
    int lane = tid & 31;
    int quarter = lane >> 3, lane8 = lane & 7;
    int g2 = lane8 >> 2, r4 = lane8 & 3;
    unsigned smask = 0xffu << (quarter << 3);
    int n = ((blockIdx.x * blockDim.x + tid) >> 5) * 4 + quarter;

    int nn = (n < N) ? n : (N - 1);
    int cnt = (n < N) ? g_deg[nn] : 0;
    if (cnt > MAXDEG) cnt = MAXDEG;

    float ssum = 0.f;
    float4 aLo = {0.f, 0.f, 0.f, 0.f}, aHi = {0.f, 0.f, 0.f, 0.f};
    edge_loop8(g_csr + (size_t)nn * MAXDEG, cnt, g_el2,
               (const uint4*)g_feat2H, g_er2[nn],
               smask, lane8, g2, r4, ssum, aLo, aHi);

    if (n < N && g2 == 0) {
        float4 bLo = ((const float4*)b2)[2 * r4];
        float4 bHi = ((const float4*)b2)[2 * r4 + 1];
        float inv = (cnt > 0) ? (1.f / ssum) : 0.f;
        float4 oLo, oHi;
        oLo.x = fmaf(aLo.x, inv, bLo.x); oLo.y = fmaf(aLo.y, inv, bLo.y);
        oLo.z = fmaf(aLo.z, inv, bLo.z); oLo.w = fmaf(aLo.w, inv, bLo.w);
        oHi.x = fmaf(aHi.x, inv, bHi.x); oHi.y = fmaf(aHi.y, inv, bHi.y);
        oHi.z = fmaf(aHi.z, inv, bHi.z); oHi.w = fmaf(aHi.w, inv, bHi.w);
        float4* out4 = (float4*)out;
        out4[(size_t)n * 8 + 2 * r4]     = oLo;
        out4[(size_t)n * 8 + 2 * r4 + 1] = oHi;
    }
}

// ---------------- driver ----------------
extern "C" void kernel_launch(void* const* d_in, const int* in_sizes, int n_in,
                              void* d_out, int out_size) {
    const float* features = (const float*)d_in[0];
    const int*   src      = (const int*)d_in[1];
    const int*   dst      = (const int*)d_in[2];
    const float* W1  = (const float*)d_in[3];
    const float* al1 = (const float*)d_in[4];
    const float* ar1 = (const float*)d_in[5];
    const float* b1  = (const float*)d_in[6];
    const float* W2  = (const float*)d_in[7];
    const float* al2 = (const float*)d_in[8];
    const float* ar2 = (const float*)d_in[9];
    const float* b2  = (const float*)d_in[10];

    int E = in_sizes[1];
    int N = in_sizes[0] / 128;
    if (N > NN) N = NN;
    if (E > EE) E = EE;

    float* out = (float*)d_out;

    static cudaStream_t s_side = nullptr;
    static cudaEvent_t ev_fork = nullptr, ev_join = nullptr;
    if (!s_side) {
        cudaStreamCreateWithFlags(&s_side, cudaStreamNonBlocking);
        cudaEventCreateWithFlags(&ev_fork, cudaEventDisableTiming);
        cudaEventCreateWithFlags(&ev_join, cudaEventDisableTiming);
    }

    const int T = 256;
    int gN = (N + T - 1) / T;
    int gE4 = (E / 4 + T) / T + 1;
    int g32 = (N + 31) / 32;       // 8 warps x 4 nodes per 256-thread block

    // fork: GEMM1 runs concurrently with CSR build
    cudaEventRecord(ev_fork, 0);
    cudaStreamWaitEvent(s_side, ev_fork, 0);
    k_gemm_attn1<<<g32, T, 0, s_side>>>(features, W1, al1, ar1, N);
    cudaEventRecord(ev_join, s_side);

    k_zero<<<gN, T>>>(N);
    k_scatter<<<gE4, T>>>(src, dst, E);

    cudaStreamWaitEvent(0, ev_join, 0);

    // layer-1 aggregate + fused GEMM2 + layer-2 projections
    k_agg1_gemm2<<<g32, T>>>(b1, W2, al2, ar2, N);
    // layer-2 aggregate -> final output
    k_agg2<<<g32, T>>>(b2, out, N);
}